// round 17
// baseline (speedup 1.0000x reference)
#include <cuda_runtime.h>
#include <cstdint>

// MFELoss: softmax over C=4, masked squared-error reduction to a scalar.
// HBM-bound streaming reduction: 128 MiB preds (fp32) + 32 MiB target (int32).
// R17: LDG and TMA both plateau at ~4.75 TB/s with DRAM only ~60% busy.
// Hypothesis: coarse 10KB stages + 1-for-1 issue behind per-stage syncthreads
// make the request stream bursty/phase-locked across the 7 CTAs per SM.
// Test: 5KB stages, 6-deep ring, 5 stages in flight per CTA; shared epilogue.
// One exact wave: 152 SMs x 7 CTAs (30KB smem/CTA), 256 thr.

#define NBLK 1064          // 152 x 7
#define NTHR 256
#define NSTAGE 6
#define AHEAD  5           // stages in flight per CTA
#define RPS   256          // rows per stage: preds 4KB + tgt 1KB = 5KB

// Per-block partials: [0]=fne_sum, [1]=fpe_sum, [2]=fne_count
static __device__ float g_part[NBLK][3];
static __device__ unsigned int g_ticket = 0;   // reset to 0 by last block each launch

__device__ __forceinline__ float rcp_fast(float x) {
    float r;
    asm("rcp.approx.f32 %0, %1;" : "=f"(r) : "f"(x));
    return r;
}

#define LOG2E 1.4426950408889634f

// OI compile-time: p_o = 1 / (1 + sum_{j!=OI} exp2((r_j - r_o)*log2e))
// fne_i = (1-p_o)^2 on target==OI rows, fpe_i = p_o^2 otherwise.
template <int OI>
__device__ __forceinline__ void accum_row_t(float4 r, int t,
                                            float& fne, float& fpe, float& cnt) {
    float ro   = (OI == 0) ? r.x : (OI == 1) ? r.y : (OI == 2) ? r.z : r.w;
    float nroL = -ro * LOG2E;
    float s = 1.0f;
    if (OI != 0) s += exp2f(fmaf(r.x, LOG2E, nroL));
    if (OI != 1) s += exp2f(fmaf(r.y, LOG2E, nroL));
    if (OI != 2) s += exp2f(fmaf(r.z, LOG2E, nroL));
    if (OI != 3) s += exp2f(fmaf(r.w, LOG2E, nroL));
    float po = rcp_fast(s);
    float d  = 1.0f - po;
    if (t == OI) { fne += d * d; cnt += 1.0f; }
    else         { fpe += po * po; }
}

__device__ __forceinline__ void mbar_wait(uint32_t mb, uint32_t phase) {
    asm volatile(
        "{\n\t"
        ".reg .pred P;\n\t"
        "W%=:\n\t"
        "mbarrier.try_wait.parity.acquire.cta.shared::cta.b64 P, [%0], %1, 0x989680;\n\t"
        "@P bra D%=;\n\t"
        "bra W%=;\n\t"
        "D%=:\n\t"
        "}"
        :: "r"(mb), "r"(phase) : "memory");
}

struct SmemState {
    float4 sp[NSTAGE][RPS];             // 24KB
    int    st[NSTAGE][RPS];             // 6KB
    unsigned long long mbar[NSTAGE];
};

// Issue stage s's two bulk copies from thread 0. OI-independent.
__device__ __forceinline__ void issue_stage(int s, int S,
                                            const float4* __restrict__ preds,
                                            const int*    __restrict__ tgt,
                                            int n_rows,
                                            uint32_t sp_base, uint32_t st_base,
                                            uint32_t mb_base)
{
    if (s >= S) return;
    long long rb  = ((long long)s * gridDim.x + blockIdx.x) * RPS;
    long long rem = (long long)n_rows - rb;
    if (rem <= 0) return;
    int valid = rem < RPS ? (int)rem : RPS;
    if (threadIdx.x == 0) {
        int b = s % NSTAGE;
        uint32_t mb = mb_base + (uint32_t)b * 8u;
        uint32_t pbytes = (uint32_t)valid * 16u;
        uint32_t tbytes = (((uint32_t)valid * 4u) + 15u) & ~15u;
        asm volatile("mbarrier.arrive.expect_tx.shared.b64 _, [%0], %1;"
                     :: "r"(mb), "r"(pbytes + tbytes) : "memory");
        asm volatile("cp.async.bulk.shared::cta.global.mbarrier::complete_tx::bytes "
                     "[%0], [%1], %2, [%3];"
                     :: "r"(sp_base + (uint32_t)b * (RPS * 16u)),
                        "l"(preds + rb), "r"(pbytes), "r"(mb) : "memory");
        asm volatile("cp.async.bulk.shared::cta.global.mbarrier::complete_tx::bytes "
                     "[%0], [%1], %2, [%3];"
                     :: "r"(st_base + (uint32_t)b * (RPS * 4u)),
                        "l"(tgt + rb), "r"(tbytes), "r"(mb) : "memory");
    }
}

// Templated stage loop (consume + keep ring full). Returns partial sums.
template <int OI>
__device__ __forceinline__ void stage_loop(SmemState& sm,
                                           const float4* __restrict__ preds,
                                           const int*    __restrict__ tgt,
                                           int n_rows, int S,
                                           uint32_t sp_base, uint32_t st_base,
                                           uint32_t mb_base,
                                           float& fne, float& fpe, float& cnt)
{
    const int tid = threadIdx.x;
    float fneL = 0.0f, fpeL = 0.0f, cntL = 0.0f;

    for (int s = 0; s < S; s++) {
        long long rb  = ((long long)s * gridDim.x + blockIdx.x) * RPS;
        long long rem = (long long)n_rows - rb;
        int b = s % NSTAGE;
        if (rem > 0) {
            int valid = rem < RPS ? (int)rem : RPS;
            mbar_wait(mb_base + (uint32_t)b * 8u, (uint32_t)((s / NSTAGE) & 1));
            if (tid < valid) {
                float4 r0 = sm.sp[b][tid];
                int    t0 = sm.st[b][tid];
                accum_row_t<OI>(r0, t0, fneL, fpeL, cntL);
            }
        }
        __syncthreads();   // all threads done with slot consumed AHEAD-1 ago
        issue_stage(s + AHEAD, S, preds, tgt, n_rows, sp_base, st_base, mb_base);
    }
    fne = fneL; fpe = fpeL; cnt = cntL;
}

__global__ void __launch_bounds__(NTHR)
mfe_tma_kernel(const float4* __restrict__ preds, const int* __restrict__ tgt,
               const int* __restrict__ oi_ptr, int n_rows, int S,
               float n_total, float* __restrict__ out)
{
    __shared__ __align__(128) SmemState sm;

    const uint32_t sp_base = (uint32_t)__cvta_generic_to_shared(&sm.sp[0][0]);
    const uint32_t st_base = (uint32_t)__cvta_generic_to_shared(&sm.st[0][0]);
    const uint32_t mb_base = (uint32_t)__cvta_generic_to_shared(&sm.mbar[0]);
    const int tid = threadIdx.x;

    if (tid == 0) {
        #pragma unroll
        for (int k = 0; k < NSTAGE; k++)
            asm volatile("mbarrier.init.shared.b64 [%0], 1;"
                         :: "r"(mb_base + k * 8) : "memory");
    }
    __syncthreads();

    // Prologue: fill the pipeline with AHEAD stages.
    #pragma unroll
    for (int k = 0; k < AHEAD; k++)
        issue_stage(k, S, preds, tgt, n_rows, sp_base, st_base, mb_base);

    const int oi = *oi_ptr;   // uniform; one specialized path executes
    float fne, fpe, cnt;
    switch (oi) {
        case 0:  stage_loop<0>(sm, preds, tgt, n_rows, S, sp_base, st_base, mb_base, fne, fpe, cnt); break;
        case 1:  stage_loop<1>(sm, preds, tgt, n_rows, S, sp_base, st_base, mb_base, fne, fpe, cnt); break;
        case 2:  stage_loop<2>(sm, preds, tgt, n_rows, S, sp_base, st_base, mb_base, fne, fpe, cnt); break;
        default: stage_loop<3>(sm, preds, tgt, n_rows, S, sp_base, st_base, mb_base, fne, fpe, cnt); break;
    }

    // ---- intra-block reduce (shared epilogue) ----
    #pragma unroll
    for (int off = 16; off > 0; off >>= 1) {
        fne += __shfl_down_sync(0xFFFFFFFFu, fne, off);
        fpe += __shfl_down_sync(0xFFFFFFFFu, fpe, off);
        cnt += __shfl_down_sync(0xFFFFFFFFu, cnt, off);
    }
    __shared__ float s_fne[NTHR / 32];
    __shared__ float s_fpe[NTHR / 32];
    __shared__ float s_cnt[NTHR / 32];
    int lane = tid & 31;
    int wid  = tid >> 5;
    if (lane == 0) { s_fne[wid] = fne; s_fpe[wid] = fpe; s_cnt[wid] = cnt; }
    __syncthreads();
    if (tid < 32) {
        float f = (lane < NTHR / 32) ? s_fne[lane] : 0.0f;
        float p = (lane < NTHR / 32) ? s_fpe[lane] : 0.0f;
        float c = (lane < NTHR / 32) ? s_cnt[lane] : 0.0f;
        #pragma unroll
        for (int off = 4; off > 0; off >>= 1) {
            f += __shfl_down_sync(0xFFFFFFFFu, f, off);
            p += __shfl_down_sync(0xFFFFFFFFu, p, off);
            c += __shfl_down_sync(0xFFFFFFFFu, c, off);
        }
        if (lane == 0) {
            g_part[blockIdx.x][0] = f;
            g_part[blockIdx.x][1] = p;
            g_part[blockIdx.x][2] = c;
        }
    }

    // ---- last-block finalize ----
    __shared__ bool s_is_last;
    __threadfence();
    __syncthreads();
    if (tid == 0) {
        unsigned int ticket = atomicAdd(&g_ticket, 1u);
        s_is_last = (ticket == (unsigned int)(gridDim.x - 1));
    }
    __syncthreads();
    if (!s_is_last) return;

    __threadfence();

    double dfne = 0.0, dfpe = 0.0, dcnt = 0.0;
    for (int i = tid; i < NBLK; i += NTHR) {
        dfne += (double)g_part[i][0];
        dfpe += (double)g_part[i][1];
        dcnt += (double)g_part[i][2];
    }
    #pragma unroll
    for (int off = 16; off > 0; off >>= 1) {
        dfne += __shfl_down_sync(0xFFFFFFFFu, dfne, off);
        dfpe += __shfl_down_sync(0xFFFFFFFFu, dfpe, off);
        dcnt += __shfl_down_sync(0xFFFFFFFFu, dcnt, off);
    }
    __shared__ double s_f[NTHR / 32], s_p[NTHR / 32], s_c[NTHR / 32];
    if (lane == 0) { s_f[wid] = dfne; s_p[wid] = dfpe; s_c[wid] = dcnt; }
    __syncthreads();
    if (tid == 0) {
        double F = 0.0, P = 0.0, Cn = 0.0;
        #pragma unroll
        for (int w = 0; w < NTHR / 32; w++) { F += s_f[w]; P += s_p[w]; Cn += s_c[w]; }
        float fne_num = (float)Cn;
        float fpe_num = n_total - fne_num;
        out[0] = (float)(P / (double)fpe_num + F / (double)fne_num);
        __threadfence();
        g_ticket = 0;                // deterministic reset for next graph replay
    }
}

extern "C" void kernel_launch(void* const* d_in, const int* in_sizes, int n_in,
                              void* d_out, int out_size)
{
    const float4* preds  = (const float4*)d_in[0];
    const int*    tgt    = (const int*)d_in[1];
    const int*    oi_ptr = (const int*)d_in[2];
    float*        out    = (float*)d_out;

    int n_rows = in_sizes[0] / 4;   // B
    long long per_wave = (long long)NBLK * RPS;
    int S = (int)(((long long)n_rows + per_wave - 1) / per_wave);

    mfe_tma_kernel<<<NBLK, NTHR>>>(preds, tgt, oi_ptr, n_rows, S, (float)n_rows, out);
}